// round 8
// baseline (speedup 1.0000x reference)
#include <cuda_runtime.h>

// Problem constants
#define BB      4096
#define NHID    512
#define BR      32
#define N2      1024            // level-2 node count (label >> 5)
#define WSTRIDE (NHID * BR)     // floats per node = 16384
#define MAXT    2592            // max tasks: 512 (L0) + 544 (L1) + 1536 (L2)

// Scratch (allocation-free rule: __device__ globals)
__device__ int   d_start[N2 + 1];
__device__ int   d_order[BB];
__device__ int4  d_tasks[MAXT];     // {node, base, cnt, level}
__device__ int   d_ntasks;
__device__ float d_probs[3 * BB];   // [level][sample]
__device__ int   d_done[BB];        // per-sample completion counter

// ---------------------------------------------------------------------------
// Fused setup: histogram + warp-shuffle scan + scatter + task list (ONE block)
// ---------------------------------------------------------------------------
__global__ void __launch_bounds__(N2)
k_setup(const int* __restrict__ labels) {
    __shared__ int cnt[N2];
    __shared__ int cur[N2];
    __shared__ int wsum[32];
    __shared__ int ctr;
    int t    = threadIdx.x;
    int lane = t & 31;
    int wid  = t >> 5;

    cnt[t] = 0;
    if (t == 0) ctr = 512;          // tasks 0..511 reserved for level 0
    // zero per-sample completion counters (graph replays need this every call)
    #pragma unroll
    for (int r = 0; r < BB / N2; r++) d_done[t + r * N2] = 0;
    __syncthreads();

    // histogram over level-2 nodes (smem atomics)
    #pragma unroll
    for (int r = 0; r < BB / N2; r++)
        atomicAdd(&cnt[(labels[t + r * N2] >> 5) & (N2 - 1)], 1);
    __syncthreads();

    int c = cnt[t];

    // ---- inclusive scan: warp shfl scan + warp-sum scan (barrier-light) ----
    int val = c;
    #pragma unroll
    for (int off = 1; off < 32; off <<= 1) {
        int v = __shfl_up_sync(0xffffffffu, val, off);
        if (lane >= off) val += v;
    }
    if (lane == 31) wsum[wid] = val;
    __syncthreads();
    if (wid == 0) {
        int v2 = wsum[lane];
        #pragma unroll
        for (int off = 1; off < 32; off <<= 1) {
            int u = __shfl_up_sync(0xffffffffu, v2, off);
            if (lane >= off) v2 += u;
        }
        wsum[lane] = v2;
    }
    __syncthreads();
    int incl = val + (wid ? wsum[wid - 1] : 0);   // inclusive prefix sum

    d_start[t + 1] = incl;
    if (t == 0) d_start[0] = 0;
    cur[t] = incl - c;              // exclusive prefix = scatter cursor
    __syncthreads();

    // scatter sample ids into node-sorted order
    #pragma unroll
    for (int r = 0; r < BB / N2; r++) {
        int i = t + r * N2;
        int n = (labels[i] >> 5) & (N2 - 1);
        d_order[atomicAdd(&cur[n], 1)] = i;
    }

    // ---- build task list ----
    // level 0: 512 fixed tasks (node 0, any 8 samples each, identity order ok)
    if (t < 512) d_tasks[t] = make_int4(0, t * 8, 8, 0);

    // level 2: node t covers sorted range [incl-c, incl)
    {
        int s = incl - c, e = incl, n = e - s;
        if (n > 0) {
            int k = (n + 7) >> 3;
            int pos = atomicAdd(&ctr, k);
            for (int i = 0; i < k; i++) {
                int b = s + i * 8;
                d_tasks[pos + i] = make_int4(33 + t, b, min(8, e - b), 2);
            }
        }
    }

    // level 1: node m covers level-2 nodes [32m, 32m+32)
    __syncthreads();                // d_start fully written (block-local visibility)
    if (t < 32) {
        int s = d_start[t * 32];
        int e = d_start[t * 32 + 32];
        int n = e - s;
        if (n > 0) {
            int k = (n + 7) >> 3;
            int pos = atomicAdd(&ctr, k);
            for (int i = 0; i < k; i++) {
                int b = s + i * 8;
                d_tasks[pos + i] = make_int4(1 + t, b, min(8, e - b), 1);
            }
        }
    }
    __syncthreads();
    if (t == 0) d_ntasks = ctr;
}

// ---------------------------------------------------------------------------
// Main kernel: one block per task (single node, single level, <=8 samples)
// Fused finalization: 3rd finished level for a sample writes the product.
// ---------------------------------------------------------------------------
struct Smem {
    float xs[8][NHID];          // staged inputs (16 KB)
    float part[8][8][BR];       // [warp][sample][col] partials (8 KB)
    int   sb[8];
    int   steps[8];
};

template <int S>
__device__ __forceinline__ void task_body(
    int node, int base, int level,
    const float* __restrict__ x, const int* __restrict__ labels,
    const float* __restrict__ W, float* __restrict__ out, Smem& sm)
{
    int tid  = threadIdx.x;
    int lane = tid & 31;
    int w    = tid >> 5;
    int c4   = lane & 7;        // column group (4 cols)
    int rg   = lane >> 3;       // row-in-group 0..3

    if (tid < S) {
        int bi = d_order[base + tid];
        sm.sb[tid] = bi;
        int lab = labels[bi];
        sm.steps[tid] = (lab >> (10 - 5 * level)) & 31;
    }
    __syncthreads();

    // stage S input rows (float4 coalesced)
    for (int i = tid; i < S * (NHID / 4); i += 256) {
        int s  = i >> 7;
        int h4 = i & 127;
        reinterpret_cast<float4*>(sm.xs[s])[h4] =
            reinterpret_cast<const float4*>(x + (size_t)sm.sb[s] * NHID)[h4];
    }
    __syncthreads();

    // GEMV partials: warp w covers h in [w*64, w*64+64), LDG.128 weights
    const float4* Wp4 = reinterpret_cast<const float4*>(
        W + (size_t)node * WSTRIDE + (size_t)w * 64 * BR);

    float acc[S][4];
    #pragma unroll
    for (int s = 0; s < S; s++) {
        acc[s][0] = 0.f; acc[s][1] = 0.f; acc[s][2] = 0.f; acc[s][3] = 0.f;
    }

    #pragma unroll 8
    for (int hb = 0; hb < 16; hb++) {
        float4 wv = Wp4[hb * 32 + lane];
        int h = w * 64 + hb * 4 + rg;
        #pragma unroll
        for (int s = 0; s < S; s++) {
            float xv = sm.xs[s][h];          // broadcast across c4 lanes
            acc[s][0] = fmaf(xv, wv.x, acc[s][0]);
            acc[s][1] = fmaf(xv, wv.y, acc[s][1]);
            acc[s][2] = fmaf(xv, wv.z, acc[s][2]);
            acc[s][3] = fmaf(xv, wv.w, acc[s][3]);
        }
    }

    // reduce across the 4 row-groups (lane bits 3,4)
    #pragma unroll
    for (int s = 0; s < S; s++) {
        #pragma unroll
        for (int k = 0; k < 4; k++) {
            acc[s][k] += __shfl_xor_sync(0xffffffffu, acc[s][k], 8);
            acc[s][k] += __shfl_xor_sync(0xffffffffu, acc[s][k], 16);
        }
    }
    if (rg == 0) {
        #pragma unroll
        for (int s = 0; s < S; s++)
            *reinterpret_cast<float4*>(&sm.part[w][s][c4 * 4]) =
                make_float4(acc[s][0], acc[s][1], acc[s][2], acc[s][3]);
    }
    __syncthreads();

    // softmax: warp w handles sample w (w < S)
    if (w < S) {
        int s = w;
        float logit = 0.0f;
        #pragma unroll
        for (int ww = 0; ww < 8; ww++) logit += sm.part[ww][s][lane];

        float mx = logit;
        #pragma unroll
        for (int o = 16; o > 0; o >>= 1)
            mx = fmaxf(mx, __shfl_xor_sync(0xffffffffu, mx, o));
        float e = __expf(logit - mx);
        float sum = e;
        #pragma unroll
        for (int o = 16; o > 0; o >>= 1)
            sum += __shfl_xor_sync(0xffffffffu, sum, o);
        float esel = __shfl_sync(0xffffffffu, e, sm.steps[s]);

        if (lane == 0) {
            int bi = sm.sb[s];
            d_probs[level * BB + bi] = esel / sum;
            __threadfence();                      // publish prob before counting
            int r = atomicAdd(&d_done[bi], 1);
            if (r == 2) {                         // last of the 3 levels
                __threadfence();                  // acquire others' probs
                volatile float* vp = d_probs;
                out[bi] = vp[bi] * vp[BB + bi] * vp[2 * BB + bi];
            }
        }
    }
}

__global__ void __launch_bounds__(256)
k_main(const float* __restrict__ x, const int* __restrict__ labels,
       const float* __restrict__ W, float* __restrict__ out)
{
    __shared__ Smem sm;
    int idx = blockIdx.x;
    if (idx >= d_ntasks) return;
    int4 tk = d_tasks[idx];
    int node = tk.x, base = tk.y, cnt = tk.z, level = tk.w;

    switch (cnt) {
        case 8: task_body<8>(node, base, level, x, labels, W, out, sm); break;
        case 7: task_body<7>(node, base, level, x, labels, W, out, sm); break;
        case 6: task_body<6>(node, base, level, x, labels, W, out, sm); break;
        case 5: task_body<5>(node, base, level, x, labels, W, out, sm); break;
        case 4: task_body<4>(node, base, level, x, labels, W, out, sm); break;
        case 3: task_body<3>(node, base, level, x, labels, W, out, sm); break;
        case 2: task_body<2>(node, base, level, x, labels, W, out, sm); break;
        default: task_body<1>(node, base, level, x, labels, W, out, sm); break;
    }
}

// ---------------------------------------------------------------------------
extern "C" void kernel_launch(void* const* d_in, const int* in_sizes, int n_in,
                              void* d_out, int out_size)
{
    const float* x      = (const float*)d_in[0];   // (4096, 512) f32
    const int*   labels = (const int*)d_in[1];     // (4096,) i32
    const float* W      = (const float*)d_in[2];   // (1057, 512, 32) f32
    float* out = (float*)d_out;                    // (4096,) f32

    k_setup<<<1, N2>>>(labels);
    k_main<<<MAXT, 256>>>(x, labels, W, out);
}